// round 16
// baseline (speedup 1.0000x reference)
#include <cuda_runtime.h>
#include <cuda_fp16.h>
#include <cstdint>

#define NN 50000
#define NE 400000
#define FULLM 0xffffffffu
#define FSTRIDE 264   // halves per padded SMEM row (256 + 8)

// G accumulator: [NN][256] fp16 (kk = cell*4 + i). Zero at module load;
// node_k re-zeroes after consuming -> every launch/replay sees zeroed scratch.
__device__ __half g_G[(size_t)NN * 256];
__device__ int    g_cnt[NN];
// Pre-packed MMA B fragments: [ks(16)][nt(8)][lane(32)] x 4 halves (32KB).
__device__ __half g_Bfrag[16 * 8 * 32 * 4];
// Gathered node features (x0,x1,x2,x6), 16B aligned.
__device__ float4 g_x4[NN];

__device__ __forceinline__ float tanh_fast(float v) {
    float y;
    asm("tanh.approx.f32 %0, %1;" : "=f"(y) : "f"(v));
    return y;
}

// ---------------------------------------------------------------------------
// Kernel 0: pack — build aligned x4 gather array + MMA B fragments.
// ---------------------------------------------------------------------------
__global__ void __launch_bounds__(256) pack_k(const float* __restrict__ x,
                                              const float* __restrict__ filters) {
    const int t = blockIdx.x * blockDim.x + threadIdx.x;
    if (t < NN) {
        const float* xp = x + t * 7;
        g_x4[t] = make_float4(xp[0], xp[1], xp[2], xp[6]);
    }
    if (t < 4096) {
        // entry (ks, nt, l): b0 = FhT[nt*8+l/4][ks*16+2*(l%4)+{0,1}],
        //                    b1 = same row, col +8.  FhT[c][kk]=filters[kk*64+c]
        const int l = t & 31, nt = (t >> 5) & 7, ks = t >> 8;
        const int c = nt * 8 + (l >> 2);
        const int k0 = ks * 16 + 2 * (l & 3);
        __half h[4];
        h[0] = __float2half_rn(filters[(k0 + 0) * 64 + c]);
        h[1] = __float2half_rn(filters[(k0 + 1) * 64 + c]);
        h[2] = __float2half_rn(filters[(k0 + 8) * 64 + c]);
        h[3] = __float2half_rn(filters[(k0 + 9) * 64 + c]);
        *(uint2*)&g_Bfrag[t * 4] = *(const uint2*)h;
    }
}

// ---------------------------------------------------------------------------
// Kernel 1: edge kernel — scatter bilinear weights into fp16 G.
// One lane per edge; gathers via aligned float4 (1 sector per endpoint);
// 8x red.global.add.noftz.v2.f16x2 per valid edge.
// ---------------------------------------------------------------------------
__global__ void __launch_bounds__(256) edge_k(const int* __restrict__ ei) {
    const int e = blockIdx.x * blockDim.x + threadIdx.x;
    if (e >= NE) return;
    const int row = ei[e];
    const int col = ei[NE + e];
    atomicAdd(&g_cnt[row], 1);  // count ALL edges (reference semantics)
    const float4 xr = g_x4[row];
    const float4 xc = g_x4[col];
    const float e0 = xc.x, e1 = xc.y, e2 = xc.z, e3 = xc.w;
    const float rx = e0 - xr.x;
    const float ry = e1 - xr.y;
    const float rz = e2 - xr.z;
    const float d2 = rx * rx + ry * ry + rz * rz;
    if (d2 >= 0.25f) return;

    const float t = 1.0f - 4.0f * d2;
    const float win = t * t * t;
    const float nrm = sqrtf(d2);
    const float s = tanhf(nrm) / (nrm + 1e-8f);
    // axis reversal: a<-z, b<-y, c<-x
    const float a = (rz * s + 1.0f) * 1.5f;
    const float b = (ry * s + 1.0f) * 1.5f;
    const float c = (rx * s + 1.0f) * 1.5f;
    const float af = floorf(a), bf = floorf(b), cf = floorf(c);
    const int a0 = (int)af, b0 = (int)bf, c0 = (int)cf;
    const float ad = a - af, bd = b - bf, cd = c - cf;
    const int ia[2] = {a0, min(a0 + 1, 3)};
    const int ib[2] = {b0, min(b0 + 1, 3)};
    const int ic[2] = {c0, min(c0 + 1, 3)};
    const float wa[2] = {1.0f - ad, ad};
    const float wb[2] = {1.0f - bd, bd};
    const float wcc[2] = {1.0f - cd, cd};

    __half* gr = g_G + (size_t)row * 256;
#pragma unroll
    for (int ka = 0; ka < 2; ka++)
#pragma unroll
        for (int kb = 0; kb < 2; kb++)
#pragma unroll
            for (int kc = 0; kc < 2; kc++) {
                const int cell = ia[ka] * 16 + ib[kb] * 4 + ic[kc];
                const float wk = win * wa[ka] * wb[kb] * wcc[kc];
                const __half2 h01 = __floats2half2_rn(wk * e0, wk * e1);
                const __half2 h23 = __floats2half2_rn(wk * e2, wk * e3);
                const uint32_t u01 = *reinterpret_cast<const uint32_t*>(&h01);
                const uint32_t u23 = *reinterpret_cast<const uint32_t*>(&h23);
                asm volatile("red.global.add.noftz.v2.f16x2 [%0], {%1,%2};"
                             :: "l"(gr + cell * 4), "r"(u01), "r"(u23)
                             : "memory");
            }
}

// ---------------------------------------------------------------------------
// Kernel 2: node GEMM + epilogue. 64-ROW CTAs (128 threads, 4 warps).
// Smaller barrier domains + ~6 CTAs/SM -> staging of one CTA overlaps
// MMA/epilogue of neighbors. G staged via cp.async into padded SMEM;
// B fragments via coalesced LDG.64 from g_Bfrag (L1-resident).
// Dynamic SMEM layout (bytes):
//   Gs   @      0 : 64*264*2 = 33792
//   par  @  33792 : 68*8*4   =  2176
//   bos  @  35968 : 16
//   scnt @  35984 : 64*4     -> total 36240
// ---------------------------------------------------------------------------
#define SMEM_TOTAL 36240

__global__ void __launch_bounds__(128) node_k(const float* __restrict__ x,
                                              const float* __restrict__ gamma,
                                              const float* __restrict__ beta,
                                              const float* __restrict__ W,
                                              const float* __restrict__ bo,
                                              float* __restrict__ out) {
    extern __shared__ char smem[];
    __half* Gs   = (__half*)smem;
    float*  par  = (float*)(smem + 33792);
    float*  bos  = (float*)(smem + 35968);
    int*    scnt = (int*)(smem + 35984);

    const int tid = threadIdx.x;
    const int base_row = blockIdx.x * 64;
    const uint32_t gs_base = (uint32_t)__cvta_generic_to_shared(Gs);

    // issue async G-tile copies (16B per chunk; 32 chunks per row)
    for (int idx = tid; idx < 64 * 32; idx += 128) {
        const int row = idx >> 5, c = idx & 31;
        const int gr = base_row + row;
        const uint32_t dst = gs_base + row * (FSTRIDE * 2) + c * 16;
        if (gr < NN) {
            const __half* src = g_G + (size_t)gr * 256 + c * 8;
            asm volatile("cp.async.ca.shared.global [%0], [%1], 16;"
                         :: "r"(dst), "l"(src));
        } else {
            *(uint4*)(Gs + row * FSTRIDE + c * 8) = make_uint4(0, 0, 0, 0);
        }
    }
    asm volatile("cp.async.commit_group;");

    if (tid < 68) {
        par[tid * 8 + 0] = gamma[tid];
        par[tid * 8 + 1] = beta[tid];
        par[tid * 8 + 2] = W[tid * 3 + 0];
        par[tid * 8 + 3] = W[tid * 3 + 1];
        par[tid * 8 + 4] = W[tid * 3 + 2];
    }
    if (tid < 3) bos[tid] = bo[tid];
    if (tid < 64) {
        const int gr = base_row + tid;
        if (gr < NN) { scnt[tid] = g_cnt[gr]; g_cnt[gr] = 0; }
        else scnt[tid] = 1;
    }

    asm volatile("cp.async.wait_group 0;");
    __syncthreads();

    // zero the global G tile now (stores overlap the MMA phase)
    for (int idx = tid; idx < 64 * 32; idx += 128) {
        const int row = idx >> 5, c = idx & 31;
        const int gr = base_row + row;
        if (gr < NN)
            ((uint4*)(g_G + (size_t)gr * 256))[c] = make_uint4(0, 0, 0, 0);
    }

    const int wid = tid >> 5, lane = tid & 31;
    const int mrow = wid * 16;
    if (base_row + mrow >= NN) return;   // tail-CTA warps with no rows

    const uint32_t a_base = gs_base + (mrow + (lane & 15)) * (FSTRIDE * 2)
                            + ((lane >> 4) * 16);
    const uint2* __restrict__ bfrag =
        (const uint2*)g_Bfrag + lane;     // + (ks*8+nt)*32 entries

    float acc[8][4];
#pragma unroll
    for (int nt = 0; nt < 8; nt++)
#pragma unroll
        for (int j = 0; j < 4; j++) acc[nt][j] = 0.f;

#pragma unroll
    for (int ks = 0; ks < 16; ks++) {
        uint32_t a0, a1, a2, a3;
        asm volatile("ldmatrix.sync.aligned.m8n8.x4.shared.b16 {%0,%1,%2,%3}, [%4];"
                     : "=r"(a0), "=r"(a1), "=r"(a2), "=r"(a3)
                     : "r"(a_base + ks * 32));
#pragma unroll
        for (int nt = 0; nt < 8; nt++) {
            const uint2 b = __ldg(bfrag + (ks * 8 + nt) * 32);
            asm volatile(
                "mma.sync.aligned.m16n8k16.row.col.f32.f16.f16.f32 "
                "{%0,%1,%2,%3}, {%4,%5,%6,%7}, {%8,%9}, {%0,%1,%2,%3};"
                : "+f"(acc[nt][0]), "+f"(acc[nt][1]),
                  "+f"(acc[nt][2]), "+f"(acc[nt][3])
                : "r"(a0), "r"(a1), "r"(a2), "r"(a3), "r"(b.x), "r"(b.y));
        }
    }

    // ---- epilogue: rows r0 (acc[.][0,1]) and r1 (acc[.][2,3]) ----
    const int g = lane >> 2, tg = lane & 3;
    const int lr0 = mrow + g, lr1 = mrow + g + 8;
    const int r0 = base_row + lr0, r1 = base_row + lr1;
    const float inv0 = 1.0f / (float)max(scnt[lr0], 1);
    const float inv1 = 1.0f / (float)max(scnt[lr1], 1);

    float hv0[16], hv1[16];
#pragma unroll
    for (int nt = 0; nt < 8; nt++) {
        hv0[nt * 2 + 0] = tanh_fast(acc[nt][0] * inv0);
        hv0[nt * 2 + 1] = tanh_fast(acc[nt][1] * inv0);
        hv1[nt * 2 + 0] = tanh_fast(acc[nt][2] * inv1);
        hv1[nt * 2 + 1] = tanh_fast(acc[nt][3] * inv1);
    }
    const int exi = (tg < 3) ? tg : 6;
    const float xv0 = x[r0 * 7 + exi];
    const float xv1 = x[r1 * 7 + exi];

    float s0 = xv0, s1 = xv1;
#pragma unroll
    for (int j = 0; j < 16; j++) { s0 += hv0[j]; s1 += hv1[j]; }
    s0 += __shfl_xor_sync(FULLM, s0, 1); s0 += __shfl_xor_sync(FULLM, s0, 2);
    s1 += __shfl_xor_sync(FULLM, s1, 1); s1 += __shfl_xor_sync(FULLM, s1, 2);
    const float mean0 = s0 * (1.0f / 68.0f);
    const float mean1 = s1 * (1.0f / 68.0f);

    float q0 = (xv0 - mean0) * (xv0 - mean0);
    float q1 = (xv1 - mean1) * (xv1 - mean1);
#pragma unroll
    for (int j = 0; j < 16; j++) {
        const float d0 = hv0[j] - mean0; q0 += d0 * d0;
        const float d1 = hv1[j] - mean1; q1 += d1 * d1;
    }
    q0 += __shfl_xor_sync(FULLM, q0, 1); q0 += __shfl_xor_sync(FULLM, q0, 2);
    q1 += __shfl_xor_sync(FULLM, q1, 1); q1 += __shfl_xor_sync(FULLM, q1, 2);
    const float rstd0 = rsqrtf(q0 * (1.0f / 68.0f) + 1e-5f);
    const float rstd1 = rsqrtf(q1 * (1.0f / 68.0f) + 1e-5f);

    float p00 = 0.f, p01 = 0.f, p02 = 0.f;
    float p10 = 0.f, p11 = 0.f, p12 = 0.f;
#pragma unroll
    for (int nt = 0; nt < 8; nt++)
#pragma unroll
        for (int j = 0; j < 2; j++) {
            const int cat = 4 + nt * 8 + 2 * tg + j;
            const float4 pr = *(const float4*)&par[cat * 8];  // g,b,w0,w1
            const float w2 = par[cat * 8 + 4];
            const float y0 = (hv0[nt * 2 + j] - mean0) * rstd0 * pr.x + pr.y;
            const float y1 = (hv1[nt * 2 + j] - mean1) * rstd1 * pr.x + pr.y;
            p00 += y0 * pr.z; p01 += y0 * pr.w; p02 += y0 * w2;
            p10 += y1 * pr.z; p11 += y1 * pr.w; p12 += y1 * w2;
        }
    {   // enc channel (cat idx = tg)
        const float4 pr = *(const float4*)&par[tg * 8];
        const float w2 = par[tg * 8 + 4];
        const float y0 = (xv0 - mean0) * rstd0 * pr.x + pr.y;
        const float y1 = (xv1 - mean1) * rstd1 * pr.x + pr.y;
        p00 += y0 * pr.z; p01 += y0 * pr.w; p02 += y0 * w2;
        p10 += y1 * pr.z; p11 += y1 * pr.w; p12 += y1 * w2;
    }
#pragma unroll
    for (int o = 1; o <= 2; o <<= 1) {
        p00 += __shfl_xor_sync(FULLM, p00, o);
        p01 += __shfl_xor_sync(FULLM, p01, o);
        p02 += __shfl_xor_sync(FULLM, p02, o);
        p10 += __shfl_xor_sync(FULLM, p10, o);
        p11 += __shfl_xor_sync(FULLM, p11, o);
        p12 += __shfl_xor_sync(FULLM, p12, o);
    }
    if (tg == 0) {
        out[r0 * 3 + 0] = p00 + bos[0];
        out[r0 * 3 + 1] = p01 + bos[1];
        out[r0 * 3 + 2] = p02 + bos[2];
        out[r1 * 3 + 0] = p10 + bos[0];
        out[r1 * 3 + 1] = p11 + bos[1];
        out[r1 * 3 + 2] = p12 + bos[2];
    }
}

// ---------------------------------------------------------------------------
extern "C" void kernel_launch(void* const* d_in, const int* in_sizes, int n_in,
                              void* d_out, int out_size) {
    const float* x       = (const float*)d_in[0];
    const int*   ei      = (const int*)d_in[1];
    const float* filters = (const float*)d_in[2];
    const float* gamma   = (const float*)d_in[3];
    const float* beta    = (const float*)d_in[4];
    const float* W       = (const float*)d_in[5];
    const float* bo      = (const float*)d_in[6];
    float* out = (float*)d_out;

    cudaFuncSetAttribute(node_k, cudaFuncAttributeMaxDynamicSharedMemorySize,
                         SMEM_TOTAL);

    pack_k<<<(NN + 255) / 256, 256>>>(x, filters);
    edge_k<<<(NE + 255) / 256, 256>>>(ei);
    node_k<<<(NN + 63) / 64, 128, SMEM_TOTAL>>>(x, gamma, beta, W, bo, out);
}

// round 17
// speedup vs baseline: 1.0135x; 1.0135x over previous
#include <cuda_runtime.h>
#include <cuda_fp16.h>
#include <cstdint>

#define NN 50000
#define NE 400000
#define FULLM 0xffffffffu
#define FSTRIDE 264   // halves per padded SMEM row (256 + 8)

// G accumulator: [NN][256] fp16 (kk = cell*4 + i). Zero at module load;
// node_k re-zeroes after consuming -> every launch/replay sees zeroed scratch.
__device__ __half g_G[(size_t)NN * 256];
__device__ int    g_cnt[NN];
// Pre-packed MMA B fragments: [ks(16)][nt(8)][lane(32)] x 4 halves (32KB).
// Written (same values) by edge_k every launch; read by node_k.
__device__ __half g_Bfrag[16 * 8 * 32 * 4];

__device__ __forceinline__ float tanh_fast(float v) {
    float y;
    asm("tanh.approx.f32 %0, %1;" : "=f"(y) : "f"(v));
    return y;
}

// ---------------------------------------------------------------------------
// Kernel 1: edge kernel — scatter bilinear weights into fp16 G.
// One lane per edge; 8x red.global.add.noftz.v2.f16x2 per valid edge.
// First 4096 threads ALSO pack the B fragments (filters -> fp16, exact
// mma.m16n8k16 per-lane layout) — no separate pack kernel.
// ---------------------------------------------------------------------------
__global__ void __launch_bounds__(256) edge_k(const float* __restrict__ x,
                                              const int* __restrict__ ei,
                                              const float* __restrict__ filters) {
    const int e = blockIdx.x * blockDim.x + threadIdx.x;

    if (e < 4096) {
        // entry (ks, nt, l): b0 = FhT[nt*8+l/4][ks*16+2*(l%4)+{0,1}],
        //                    b1 = same row, col +8.  FhT[c][kk]=filters[kk*64+c]
        const int l = e & 31, nt = (e >> 5) & 7, ks = e >> 8;
        const int c = nt * 8 + (l >> 2);
        const int k0 = ks * 16 + 2 * (l & 3);
        __half h[4];
        h[0] = __float2half_rn(filters[(k0 + 0) * 64 + c]);
        h[1] = __float2half_rn(filters[(k0 + 1) * 64 + c]);
        h[2] = __float2half_rn(filters[(k0 + 8) * 64 + c]);
        h[3] = __float2half_rn(filters[(k0 + 9) * 64 + c]);
        *(uint2*)&g_Bfrag[e * 4] = *(const uint2*)h;
    }

    if (e >= NE) return;
    const int row = ei[e];
    const int col = ei[NE + e];
    atomicAdd(&g_cnt[row], 1);  // count ALL edges (reference semantics)
    const float* xr = x + row * 7;
    const float* xc = x + col * 7;
    const float e0 = xc[0], e1 = xc[1], e2 = xc[2], e3 = xc[6];
    const float rx = e0 - xr[0];
    const float ry = e1 - xr[1];
    const float rz = e2 - xr[2];
    const float d2 = rx * rx + ry * ry + rz * rz;
    if (d2 >= 0.25f) return;

    const float t = 1.0f - 4.0f * d2;
    const float win = t * t * t;
    const float nrm = sqrtf(d2);
    const float s = tanhf(nrm) / (nrm + 1e-8f);
    // axis reversal: a<-z, b<-y, c<-x
    const float a = (rz * s + 1.0f) * 1.5f;
    const float b = (ry * s + 1.0f) * 1.5f;
    const float c = (rx * s + 1.0f) * 1.5f;
    const float af = floorf(a), bf = floorf(b), cf = floorf(c);
    const int a0 = (int)af, b0 = (int)bf, c0 = (int)cf;
    const float ad = a - af, bd = b - bf, cd = c - cf;
    const int ia[2] = {a0, min(a0 + 1, 3)};
    const int ib[2] = {b0, min(b0 + 1, 3)};
    const int ic[2] = {c0, min(c0 + 1, 3)};
    const float wa[2] = {1.0f - ad, ad};
    const float wb[2] = {1.0f - bd, bd};
    const float wcc[2] = {1.0f - cd, cd};

    __half* gr = g_G + (size_t)row * 256;
#pragma unroll
    for (int ka = 0; ka < 2; ka++)
#pragma unroll
        for (int kb = 0; kb < 2; kb++)
#pragma unroll
            for (int kc = 0; kc < 2; kc++) {
                const int cell = ia[ka] * 16 + ib[kb] * 4 + ic[kc];
                const float wk = win * wa[ka] * wb[kb] * wcc[kc];
                const __half2 h01 = __floats2half2_rn(wk * e0, wk * e1);
                const __half2 h23 = __floats2half2_rn(wk * e2, wk * e3);
                const uint32_t u01 = *reinterpret_cast<const uint32_t*>(&h01);
                const uint32_t u23 = *reinterpret_cast<const uint32_t*>(&h23);
                asm volatile("red.global.add.noftz.v2.f16x2 [%0], {%1,%2};"
                             :: "l"(gr + cell * 4), "r"(u01), "r"(u23)
                             : "memory");
            }
}

// ---------------------------------------------------------------------------
// Kernel 2: node GEMM + epilogue. 64-ROW CTAs (128 threads, 4 warps).
// Smaller barrier domains + ~6 CTAs/SM -> staging of one CTA overlaps
// MMA/epilogue of neighbors; grid 782 fits one wave. G staged via cp.async
// into padded SMEM; B fragments via coalesced LDG.64 from g_Bfrag
// (L1-resident after first touch).
// Dynamic SMEM layout (bytes):
//   Gs   @      0 : 64*264*2 = 33792
//   par  @  33792 : 68*8*4   =  2176
//   bos  @  35968 : 16
//   scnt @  35984 : 64*4     -> total 36240
// ---------------------------------------------------------------------------
#define SMEM_TOTAL 36240

__global__ void __launch_bounds__(128) node_k(const float* __restrict__ x,
                                              const float* __restrict__ gamma,
                                              const float* __restrict__ beta,
                                              const float* __restrict__ W,
                                              const float* __restrict__ bo,
                                              float* __restrict__ out) {
    extern __shared__ char smem[];
    __half* Gs   = (__half*)smem;
    float*  par  = (float*)(smem + 33792);
    float*  bos  = (float*)(smem + 35968);
    int*    scnt = (int*)(smem + 35984);

    const int tid = threadIdx.x;
    const int base_row = blockIdx.x * 64;
    const uint32_t gs_base = (uint32_t)__cvta_generic_to_shared(Gs);

    // issue async G-tile copies (16B per chunk; 32 chunks per row)
    for (int idx = tid; idx < 64 * 32; idx += 128) {
        const int row = idx >> 5, c = idx & 31;
        const int gr = base_row + row;
        const uint32_t dst = gs_base + row * (FSTRIDE * 2) + c * 16;
        if (gr < NN) {
            const __half* src = g_G + (size_t)gr * 256 + c * 8;
            asm volatile("cp.async.ca.shared.global [%0], [%1], 16;"
                         :: "r"(dst), "l"(src));
        } else {
            *(uint4*)(Gs + row * FSTRIDE + c * 8) = make_uint4(0, 0, 0, 0);
        }
    }
    asm volatile("cp.async.commit_group;");

    if (tid < 68) {
        par[tid * 8 + 0] = gamma[tid];
        par[tid * 8 + 1] = beta[tid];
        par[tid * 8 + 2] = W[tid * 3 + 0];
        par[tid * 8 + 3] = W[tid * 3 + 1];
        par[tid * 8 + 4] = W[tid * 3 + 2];
    }
    if (tid < 3) bos[tid] = bo[tid];
    if (tid < 64) {
        const int gr = base_row + tid;
        if (gr < NN) { scnt[tid] = g_cnt[gr]; g_cnt[gr] = 0; }
        else scnt[tid] = 1;
    }

    asm volatile("cp.async.wait_group 0;");
    __syncthreads();

    // zero the global G tile now (stores overlap the MMA phase)
    for (int idx = tid; idx < 64 * 32; idx += 128) {
        const int row = idx >> 5, c = idx & 31;
        const int gr = base_row + row;
        if (gr < NN)
            ((uint4*)(g_G + (size_t)gr * 256))[c] = make_uint4(0, 0, 0, 0);
    }

    const int wid = tid >> 5, lane = tid & 31;
    const int mrow = wid * 16;
    if (base_row + mrow >= NN) return;   // tail-CTA warps with no rows

    const uint32_t a_base = gs_base + (mrow + (lane & 15)) * (FSTRIDE * 2)
                            + ((lane >> 4) * 16);
    const uint2* __restrict__ bfrag =
        (const uint2*)g_Bfrag + lane;     // + (ks*8+nt)*32 entries

    float acc[8][4];
#pragma unroll
    for (int nt = 0; nt < 8; nt++)
#pragma unroll
        for (int j = 0; j < 4; j++) acc[nt][j] = 0.f;

#pragma unroll
    for (int ks = 0; ks < 16; ks++) {
        uint32_t a0, a1, a2, a3;
        asm volatile("ldmatrix.sync.aligned.m8n8.x4.shared.b16 {%0,%1,%2,%3}, [%4];"
                     : "=r"(a0), "=r"(a1), "=r"(a2), "=r"(a3)
                     : "r"(a_base + ks * 32));
#pragma unroll
        for (int nt = 0; nt < 8; nt++) {
            const uint2 b = __ldg(bfrag + (ks * 8 + nt) * 32);
            asm volatile(
                "mma.sync.aligned.m16n8k16.row.col.f32.f16.f16.f32 "
                "{%0,%1,%2,%3}, {%4,%5,%6,%7}, {%8,%9}, {%0,%1,%2,%3};"
                : "+f"(acc[nt][0]), "+f"(acc[nt][1]),
                  "+f"(acc[nt][2]), "+f"(acc[nt][3])
                : "r"(a0), "r"(a1), "r"(a2), "r"(a3), "r"(b.x), "r"(b.y));
        }
    }

    // ---- epilogue: rows r0 (acc[.][0,1]) and r1 (acc[.][2,3]) ----
    const int g = lane >> 2, tg = lane & 3;
    const int lr0 = mrow + g, lr1 = mrow + g + 8;
    const int r0 = base_row + lr0, r1 = base_row + lr1;
    const float inv0 = 1.0f / (float)max(scnt[lr0], 1);
    const float inv1 = 1.0f / (float)max(scnt[lr1], 1);

    float hv0[16], hv1[16];
#pragma unroll
    for (int nt = 0; nt < 8; nt++) {
        hv0[nt * 2 + 0] = tanh_fast(acc[nt][0] * inv0);
        hv0[nt * 2 + 1] = tanh_fast(acc[nt][1] * inv0);
        hv1[nt * 2 + 0] = tanh_fast(acc[nt][2] * inv1);
        hv1[nt * 2 + 1] = tanh_fast(acc[nt][3] * inv1);
    }
    const int exi = (tg < 3) ? tg : 6;
    const float xv0 = x[r0 * 7 + exi];
    const float xv1 = x[r1 * 7 + exi];

    float s0 = xv0, s1 = xv1;
#pragma unroll
    for (int j = 0; j < 16; j++) { s0 += hv0[j]; s1 += hv1[j]; }
    s0 += __shfl_xor_sync(FULLM, s0, 1); s0 += __shfl_xor_sync(FULLM, s0, 2);
    s1 += __shfl_xor_sync(FULLM, s1, 1); s1 += __shfl_xor_sync(FULLM, s1, 2);
    const float mean0 = s0 * (1.0f / 68.0f);
    const float mean1 = s1 * (1.0f / 68.0f);

    float q0 = (xv0 - mean0) * (xv0 - mean0);
    float q1 = (xv1 - mean1) * (xv1 - mean1);
#pragma unroll
    for (int j = 0; j < 16; j++) {
        const float d0 = hv0[j] - mean0; q0 += d0 * d0;
        const float d1 = hv1[j] - mean1; q1 += d1 * d1;
    }
    q0 += __shfl_xor_sync(FULLM, q0, 1); q0 += __shfl_xor_sync(FULLM, q0, 2);
    q1 += __shfl_xor_sync(FULLM, q1, 1); q1 += __shfl_xor_sync(FULLM, q1, 2);
    const float rstd0 = rsqrtf(q0 * (1.0f / 68.0f) + 1e-5f);
    const float rstd1 = rsqrtf(q1 * (1.0f / 68.0f) + 1e-5f);

    float p00 = 0.f, p01 = 0.f, p02 = 0.f;
    float p10 = 0.f, p11 = 0.f, p12 = 0.f;
#pragma unroll
    for (int nt = 0; nt < 8; nt++)
#pragma unroll
        for (int j = 0; j < 2; j++) {
            const int cat = 4 + nt * 8 + 2 * tg + j;
            const float4 pr = *(const float4*)&par[cat * 8];  // g,b,w0,w1
            const float w2 = par[cat * 8 + 4];
            const float y0 = (hv0[nt * 2 + j] - mean0) * rstd0 * pr.x + pr.y;
            const float y1 = (hv1[nt * 2 + j] - mean1) * rstd1 * pr.x + pr.y;
            p00 += y0 * pr.z; p01 += y0 * pr.w; p02 += y0 * w2;
            p10 += y1 * pr.z; p11 += y1 * pr.w; p12 += y1 * w2;
        }
    {   // enc channel (cat idx = tg)
        const float4 pr = *(const float4*)&par[tg * 8];
        const float w2 = par[tg * 8 + 4];
        const float y0 = (xv0 - mean0) * rstd0 * pr.x + pr.y;
        const float y1 = (xv1 - mean1) * rstd1 * pr.x + pr.y;
        p00 += y0 * pr.z; p01 += y0 * pr.w; p02 += y0 * w2;
        p10 += y1 * pr.z; p11 += y1 * pr.w; p12 += y1 * w2;
    }
#pragma unroll
    for (int o = 1; o <= 2; o <<= 1) {
        p00 += __shfl_xor_sync(FULLM, p00, o);
        p01 += __shfl_xor_sync(FULLM, p01, o);
        p02 += __shfl_xor_sync(FULLM, p02, o);
        p10 += __shfl_xor_sync(FULLM, p10, o);
        p11 += __shfl_xor_sync(FULLM, p11, o);
        p12 += __shfl_xor_sync(FULLM, p12, o);
    }
    if (tg == 0) {
        out[r0 * 3 + 0] = p00 + bos[0];
        out[r0 * 3 + 1] = p01 + bos[1];
        out[r0 * 3 + 2] = p02 + bos[2];
        out[r1 * 3 + 0] = p10 + bos[0];
        out[r1 * 3 + 1] = p11 + bos[1];
        out[r1 * 3 + 2] = p12 + bos[2];
    }
}

// ---------------------------------------------------------------------------
extern "C" void kernel_launch(void* const* d_in, const int* in_sizes, int n_in,
                              void* d_out, int out_size) {
    const float* x       = (const float*)d_in[0];
    const int*   ei      = (const int*)d_in[1];
    const float* filters = (const float*)d_in[2];
    const float* gamma   = (const float*)d_in[3];
    const float* beta    = (const float*)d_in[4];
    const float* W       = (const float*)d_in[5];
    const float* bo      = (const float*)d_in[6];
    float* out = (float*)d_out;

    cudaFuncSetAttribute(node_k, cudaFuncAttributeMaxDynamicSharedMemorySize,
                         SMEM_TOTAL);

    edge_k<<<(NE + 255) / 256, 256>>>(x, ei, filters);
    node_k<<<(NN + 63) / 64, 128, SMEM_TOTAL>>>(x, gamma, beta, W, bo, out);
}